// round 5
// baseline (speedup 1.0000x reference)
#include <cuda_runtime.h>
#include <math.h>

#define BS 8
#define F 16
#define NI 24
#define L 16384            // H*W
#define NGRP (L / 32)      // 512 pixel-groups per batch
#define IH 12              // instances per warp (instance half)

// ---------------- scratch (no allocations allowed) ----------------
__device__ float    g_sums[BS][NI][F];
__device__ float    g_counts[BS][NI];
__device__ float    g_means[BS][NI][F];
__device__ unsigned g_masks[BS][NGRP][NI];
__device__ float    g_varnum[BS];
__device__ float    g_varden[BS];
__device__ float    g_hinge[BS];
__device__ float    g_reg[BS];

// ---------------- K0: zero accumulators ----------------
__global__ void k_zero() {
    int tid = threadIdx.x;
    for (int i = tid; i < BS * NI * F; i += blockDim.x)
        ((float*)g_sums)[i] = 0.f;
    for (int i = tid; i < BS * NI; i += blockDim.x)
        ((float*)g_counts)[i] = 0.f;
    if (tid < BS) g_varnum[tid] = 0.f;
}

// ---------------- K1: sums / counts / masks ----------------
// grid = (128, BS): blockIdx.x = blkb*2 + ih  (ih = instance half)
// warp w handles pixel-group (blkb*8 + w), instances [ih*12, ih*12+12)
__global__ void __launch_bounds__(256) k_sums(const float* __restrict__ inp,
                                              const int* __restrict__ tgt,
                                              const int* __restrict__ nobj) {
    const int b    = blockIdx.y;
    const int ih   = blockIdx.x & 1;
    const int blkb = blockIdx.x >> 1;
    const int warp = threadIdx.x >> 5;
    const int lane = threadIdx.x & 31;
    const int f    = lane & 15;
    const int half = lane >> 4;
    const int grp  = blkb * 8 + warp;             // 0..511
    const int l0   = grp * 32;
    const int i0   = ih * IH;
    const int nb   = __ldg(nobj + b);
    int ni = nb - i0; ni = ni < 0 ? 0 : (ni > IH ? IH : ni);

    __shared__ float sh_w[8][IH][F];              // 6KB partials
    __shared__ float sh_c[8][IH];

    for (int idx = threadIdx.x; idx < 8 * IH * F; idx += 256)
        ((float*)sh_w)[idx] = 0.f;
    if (threadIdx.x < 8 * IH) ((float*)sh_c)[threadIdx.x] = 0.f;
    __syncthreads();

    if (ni > 0) {
        // 16 contiguous pixels of this lane's feature row (4x LDG.128)
        const float* ip = inp + ((size_t)b * F + f) * L + l0 + half * 16;
        float4 v0 = *(const float4*)(ip + 0);
        float4 v1 = *(const float4*)(ip + 4);
        float4 v2 = *(const float4*)(ip + 8);
        float4 v3 = *(const float4*)(ip + 12);
        float preg[16] = {v0.x, v0.y, v0.z, v0.w, v1.x, v1.y, v1.z, v1.w,
                          v2.x, v2.y, v2.z, v2.w, v3.x, v3.y, v3.z, v3.w};

        // batched target loads (lane = pixel)
        const int* tb = tgt + ((size_t)b * NI + i0) * L + l0 + lane;
        int tval[IH];
#pragma unroll
        for (int j = 0; j < IH; j++)
            tval[j] = (j < ni) ? tb[(size_t)j * L] : 0;

#pragma unroll
        for (int j = 0; j < IH; j++) {
            if (j >= ni) break;                   // warp-uniform
            unsigned mi = __ballot_sync(0xffffffffu, tval[j] != 0);
            if (lane == 0) {
                g_masks[b][grp][i0 + j] = mi;
                sh_c[warp][j] = (float)__popc(mi);
            }
            unsigned sub = (mi >> (half * 16)) & 0xffffu;
            float a0 = 0.f, a1 = 0.f;
#pragma unroll
            for (int k = 0; k < 16; k += 2) {
                if ((sub >> k) & 1u)       a0 += preg[k];
                if ((sub >> (k + 1)) & 1u) a1 += preg[k + 1];
            }
            float a = a0 + a1;
            a += __shfl_down_sync(0xffffffffu, a, 16);
            if (lane < 16) sh_w[warp][j][f] = a;
        }
    }
    __syncthreads();

    // block tree-reduce -> one global atomic per (i,f)
    for (int idx = threadIdx.x; idx < IH * F; idx += 256) {
        int j = idx >> 4, ff = idx & 15;
        if (i0 + j < nb) {
            float s = 0.f;
#pragma unroll
            for (int w = 0; w < 8; w++) s += sh_w[w][j][ff];
            atomicAdd(&g_sums[b][i0 + j][ff], s);
        }
    }
    if (threadIdx.x < IH && i0 + threadIdx.x < nb) {
        float s = 0.f;
#pragma unroll
        for (int w = 0; w < 8; w++) s += sh_c[w][threadIdx.x];
        atomicAdd(&g_counts[b][i0 + threadIdx.x], s);
    }
}

// ---------------- K2: means, var_den, hinge(dist), reg ----------------
__global__ void k_stats(const int* __restrict__ nobj_arr) {
    __shared__ float sh_h[BS], sh_r[BS], sh_v[BS];
    const int tid = threadIdx.x;
    if (tid < BS) { sh_h[tid] = 0.f; sh_r[tid] = 0.f; sh_v[tid] = 0.f; }
    __syncthreads();

    for (int idx = tid; idx < BS * NI * F; idx += blockDim.x) {
        int b = idx / (NI * F);
        int i = (idx % (NI * F)) >> 4;
        int nb = nobj_arr[b];
        float mval = 0.f;
        if (i < nb) {
            float c = g_counts[b][i];
            mval = ((float*)g_sums)[idx] / (c > 0.f ? c : 1.f);
        }
        ((float*)g_means)[idx] = mval;
    }
    __syncthreads();

    for (int idx = tid; idx < BS * NI; idx += blockDim.x) {
        int b = idx / NI, i = idx % NI;
        if (i < nobj_arr[b]) {
            atomicAdd(&sh_v[b], g_counts[b][i]);
            float ss = 0.f;
#pragma unroll
            for (int ff = 0; ff < F; ff++) { float m = g_means[b][i][ff]; ss += m * m; }
            atomicAdd(&sh_r[b], ss > 0.f ? sqrtf(ss) : 0.f);
        }
    }
    for (int idx = tid; idx < BS * NI * NI; idx += blockDim.x) {
        int b = idx / (NI * NI);
        int r = idx % (NI * NI);
        int i = r / NI, j = r % NI;
        int nb = nobj_arr[b];
        if (i < nb && j < nb && i != j) {
            float ss = 0.f;
#pragma unroll
            for (int ff = 0; ff < F; ff++) {
                float d = g_means[b][i][ff] - g_means[b][j][ff];
                ss += d * d;
            }
            float dn = ss > 0.f ? sqrtf(ss) : 0.f;
            float h = fmaxf(3.0f - dn, 0.f);      // margin = 2*delta_d
            atomicAdd(&sh_h[b], h * h);
        }
    }
    __syncthreads();
    if (tid < BS) {
        g_varden[tid] = sh_v[tid];
        g_hinge[tid]  = sh_h[tid];
        g_reg[tid]    = sh_r[tid];
    }
}

// ---------------- K3: var_num (pixel x instance-half per thread) ----------------
// grid = (128, BS): block covers 128 pixels; tid&127 = pixel, tid>>7 = ih.
__global__ void __launch_bounds__(256) k_var(const float* __restrict__ inp,
                                             const int* __restrict__ nobj) {
    const int b    = blockIdx.y;
    const int tid  = threadIdx.x;
    const int lane = tid & 31;
    const int warp = tid >> 5;
    const int ih   = tid >> 7;                    // warp-uniform (warps 0-3 / 4-7)
    const int i0   = ih * IH;
    const int l    = blockIdx.x * 128 + (tid & 127);
    const int grp  = l >> 5;
    const int nb   = __ldg(nobj + b);
    int ni = nb - i0; ni = ni < 0 ? 0 : (ni > IH ? IH : ni);

    __shared__ ulonglong2 msh2[NI * 4];           // negated means, f32x2-packed
    __shared__ float red[8];

    for (int idx = tid; idx < NI * F; idx += 256)
        ((float*)msh2)[idx] = -((const float*)g_means)[b * NI * F + idx];
    __syncthreads();

    float local = 0.f;
    if (ni > 0) {
        // per-pixel feature vector packed into 8 f32x2 regs (lane-coalesced)
        const float* ib = inp + (size_t)b * F * L + l;
        unsigned long long p2[8];
#pragma unroll
        for (int j = 0; j < 8; j++) {
            float lo = ib[(size_t)(2 * j) * L];
            float hi = ib[(size_t)(2 * j + 1) * L];
            asm("mov.b64 %0,{%1,%2};" : "=l"(p2[j]) : "f"(lo), "f"(hi));
        }

        unsigned mw = (lane < IH) ? g_masks[b][grp][i0 + lane] : 0u;

#pragma unroll
        for (int j = 0; j < IH; j++) {
            if (j >= ni) break;
            unsigned mi = __shfl_sync(0xffffffffu, mw, j);
            if ((mi >> lane) & 1u) {
                unsigned long long ssa = 0ull, ssb = 0ull;
#pragma unroll
                for (int q = 0; q < 4; q++) {
                    ulonglong2 mv = msh2[(i0 + j) * 4 + q];
                    unsigned long long d0, d1;
                    asm("add.rn.f32x2 %0,%1,%2;" : "=l"(d0) : "l"(p2[2 * q]),     "l"(mv.x));
                    asm("add.rn.f32x2 %0,%1,%2;" : "=l"(d1) : "l"(p2[2 * q + 1]), "l"(mv.y));
                    asm("fma.rn.f32x2 %0,%1,%2,%3;" : "=l"(ssa) : "l"(d0), "l"(d0), "l"(ssa));
                    asm("fma.rn.f32x2 %0,%1,%2,%3;" : "=l"(ssb) : "l"(d1), "l"(d1), "l"(ssb));
                }
                float alo, ahi, blo, bhi;
                asm("mov.b64 {%0,%1},%2;" : "=f"(alo), "=f"(ahi) : "l"(ssa));
                asm("mov.b64 {%0,%1},%2;" : "=f"(blo), "=f"(bhi) : "l"(ssb));
                float ss = (alo + ahi) + (blo + bhi);
                if (ss > 0.25f) {                 // delta_v^2
                    float h = sqrtf(ss) - 0.5f;
                    local += h * h;
                }
            }
        }
    }

#pragma unroll
    for (int o = 16; o > 0; o >>= 1)
        local += __shfl_down_sync(0xffffffffu, local, o);
    if (lane == 0) red[warp] = local;
    __syncthreads();
    if (tid < 8) {
        float v = red[tid];
#pragma unroll
        for (int o = 4; o > 0; o >>= 1)
            v += __shfl_down_sync(0xffu, v, o);
        if (tid == 0) atomicAdd(&g_varnum[b], v);
    }
}

// ---------------- K4: finalize ----------------
__global__ void k_final(const int* __restrict__ nobj_arr, float* __restrict__ out) {
    if (threadIdx.x == 0) {
        float var_t = 0.f, dist_t = 0.f, reg_t = 0.f;
        for (int b = 0; b < BS; b++) {
            var_t += g_varnum[b] / g_varden[b];
            float nf = (float)nobj_arr[b];
            float denom = nf > 1.f ? nf * (nf - 1.f) : 1.f;
            dist_t += (nf > 1.f) ? g_hinge[b] / denom : 0.f;
            reg_t += g_reg[b] / nf;
        }
        out[0] = var_t / BS + dist_t / BS + 0.001f * (reg_t / BS);
    }
}

// ---------------- launch ----------------
extern "C" void kernel_launch(void* const* d_in, const int* in_sizes, int n_in,
                              void* d_out, int out_size) {
    const float* inp  = (const float*)d_in[0];   // (8,16,128,128) f32
    const int*   tgt  = (const int*)d_in[1];     // (8,24,128,128) i32
    const int*   nobj = (const int*)d_in[2];     // (8,1) i32
    (void)in_sizes; (void)n_in; (void)out_size;

    k_zero<<<1, 256>>>();
    dim3 g(128, BS);                             // 1024 blocks each
    k_sums<<<g, 256>>>(inp, tgt, nobj);
    k_stats<<<1, 256>>>(nobj);
    k_var<<<g, 256>>>(inp, nobj);
    k_final<<<1, 32>>>(nobj, (float*)d_out);
}

// round 6
// speedup vs baseline: 1.0247x; 1.0247x over previous
#include <cuda_runtime.h>
#include <math.h>

#define BS 8
#define F 16
#define NI 24
#define L 16384            // H*W
#define NGRP (L / 32)      // 512 pixel-groups per batch
#define IH 12              // instances per warp (instance half)
#define NBT 1024u          // total blocks per kernel (128 x 8)

// ---------------- scratch (no allocations; zero-init at load; each replay restores) ----
__device__ float    g_sums[BS][NI][F];
__device__ float    g_counts[BS][NI];
__device__ float    g_means[BS][NI][F];
__device__ float    g_mm[BS][NI];
__device__ unsigned g_masks[BS][NGRP][NI];
__device__ float    g_varnum[BS];
__device__ float    g_varden[BS];
__device__ float    g_hinge[BS];
__device__ float    g_reg[BS];
__device__ unsigned g_cnt1;
__device__ unsigned g_cnt2;

// ================= K1: sums/counts/masks + (last block) stats =================
// grid = (128, BS): blockIdx.x = blkb*2 + ih; warp handles one 32-pixel group x 12 inst.
__global__ void __launch_bounds__(256) k_sums(const float* __restrict__ inp,
                                              const int* __restrict__ tgt,
                                              const int* __restrict__ nobj) {
    const int b    = blockIdx.y;
    const int ih   = blockIdx.x & 1;
    const int blkb = blockIdx.x >> 1;
    const int tid  = threadIdx.x;
    const int warp = tid >> 5;
    const int lane = tid & 31;
    const int f    = lane & 15;
    const int half = lane >> 4;
    const int grp  = blkb * 8 + warp;             // 0..511
    const int l0   = grp * 32;
    const int i0   = ih * IH;
    const int nb   = __ldg(nobj + b);
    int ni = nb - i0; ni = ni < 0 ? 0 : (ni > IH ? IH : ni);

    __shared__ float sh_w[8][IH][F];              // 6KB partials
    __shared__ float sh_c[8][IH];
    __shared__ float smeans[BS * NI * F];         // 12KB (stats phase)
    __shared__ float sh_h[BS], sh_r[BS], sh_v[BS];
    __shared__ bool  sflag;

    for (int idx = tid; idx < 8 * IH * F; idx += 256) ((float*)sh_w)[idx] = 0.f;
    if (tid < 8 * IH) ((float*)sh_c)[tid] = 0.f;
    if (tid < BS) { sh_h[tid] = 0.f; sh_r[tid] = 0.f; sh_v[tid] = 0.f; }
    __syncthreads();

    if (ni > 0) {
        // 16 contiguous pixels of this lane's feature row (4x LDG.128)
        const float* ip = inp + ((size_t)b * F + f) * L + l0 + half * 16;
        float4 v0 = *(const float4*)(ip + 0);
        float4 v1 = *(const float4*)(ip + 4);
        float4 v2 = *(const float4*)(ip + 8);
        float4 v3 = *(const float4*)(ip + 12);
        float preg[16] = {v0.x, v0.y, v0.z, v0.w, v1.x, v1.y, v1.z, v1.w,
                          v2.x, v2.y, v2.z, v2.w, v3.x, v3.y, v3.z, v3.w};

        const int* tb = tgt + ((size_t)b * NI + i0) * L + l0 + lane;
        int tval[IH];
#pragma unroll
        for (int j = 0; j < IH; j++)
            tval[j] = (j < ni) ? tb[(size_t)j * L] : 0;

#pragma unroll
        for (int j = 0; j < IH; j++) {
            if (j >= ni) break;                   // warp-uniform
            unsigned mi = __ballot_sync(0xffffffffu, tval[j] != 0);
            if (lane == 0) {
                g_masks[b][grp][i0 + j] = mi;
                sh_c[warp][j] = (float)__popc(mi);
            }
            unsigned sub = (mi >> (half * 16)) & 0xffffu;
            float a0 = 0.f, a1 = 0.f;
#pragma unroll
            for (int k = 0; k < 16; k += 2) {
                if ((sub >> k) & 1u)       a0 += preg[k];
                if ((sub >> (k + 1)) & 1u) a1 += preg[k + 1];
            }
            float a = a0 + a1;
            a += __shfl_down_sync(0xffffffffu, a, 16);
            if (lane < 16) sh_w[warp][j][f] = a;
        }
    }
    __syncthreads();

    // block tree-reduce -> one global atomic per (i,f)
    for (int idx = tid; idx < IH * F; idx += 256) {
        int j = idx >> 4, ff = idx & 15;
        if (i0 + j < nb) {
            float s = 0.f;
#pragma unroll
            for (int w = 0; w < 8; w++) s += sh_w[w][j][ff];
            atomicAdd(&g_sums[b][i0 + j][ff], s);
        }
    }
    if (tid < IH && i0 + tid < nb) {
        float s = 0.f;
#pragma unroll
        for (int w = 0; w < 8; w++) s += sh_c[w][tid];
        atomicAdd(&g_counts[b][i0 + tid], s);
    }

    // ---- last block: means / mm / varden / reg / hinge, then re-zero scratch ----
    __threadfence();
    __syncthreads();
    if (tid == 0) sflag = (atomicAdd(&g_cnt1, 1u) == NBT - 1u);
    __syncthreads();
    if (!sflag) return;

    for (int idx = tid; idx < BS * NI * F; idx += 256) {
        int bb = idx / (NI * F);
        int i  = (idx % (NI * F)) >> 4;
        float mval = 0.f;
        if (i < __ldg(nobj + bb)) {
            float c = g_counts[bb][i];
            mval = ((float*)g_sums)[idx] / (c > 0.f ? c : 1.f);
        }
        smeans[idx] = mval;
        ((float*)g_means)[idx] = mval;
    }
    __syncthreads();

    for (int idx = tid; idx < BS * NI; idx += 256) {
        int bb = idx / NI, i = idx % NI;
        float mm = 0.f;
#pragma unroll
        for (int ff = 0; ff < F; ff++) {
            float m = smeans[idx * F + ff];
            mm += m * m;
        }
        g_mm[bb][i] = mm;
        if (i < __ldg(nobj + bb)) {
            atomicAdd(&sh_v[bb], g_counts[bb][i]);
            atomicAdd(&sh_r[bb], mm > 0.f ? sqrtf(mm) : 0.f);
        }
    }
    for (int idx = tid; idx < BS * NI * NI; idx += 256) {
        int bb = idx / (NI * NI);
        int r  = idx % (NI * NI);
        int i = r / NI, j = r % NI;
        int nbb = __ldg(nobj + bb);
        if (i < nbb && j < nbb && i != j) {
            float ss = 0.f;
#pragma unroll
            for (int ff = 0; ff < F; ff++) {
                float d = smeans[(bb * NI + i) * F + ff] - smeans[(bb * NI + j) * F + ff];
                ss += d * d;
            }
            float dn = ss > 0.f ? sqrtf(ss) : 0.f;
            float h = fmaxf(3.0f - dn, 0.f);      // margin = 2*delta_d
            atomicAdd(&sh_h[bb], h * h);
        }
    }
    __syncthreads();
    if (tid < BS) {
        g_varden[tid] = sh_v[tid];
        g_hinge[tid]  = sh_h[tid];
        g_reg[tid]    = sh_r[tid];
    }
    // re-zero for next replay (all blocks already flushed their atomics)
    for (int idx = tid; idx < BS * NI * F; idx += 256) ((float*)g_sums)[idx] = 0.f;
    for (int idx = tid; idx < BS * NI; idx += 256)     ((float*)g_counts)[idx] = 0.f;
    __syncthreads();
    if (tid == 0) g_cnt1 = 0u;
}

// ================= K2: var_num (||p||^2+||m||^2-2 p.m) + (last block) final =====
// grid = (128, BS): tid&127 = pixel within 128-px block, tid>>7 = instance half.
__global__ void __launch_bounds__(256) k_var(const float* __restrict__ inp,
                                             const int* __restrict__ nobj,
                                             float* __restrict__ out) {
    const int b    = blockIdx.y;
    const int tid  = threadIdx.x;
    const int lane = tid & 31;
    const int warp = tid >> 5;
    const int ih   = tid >> 7;                    // warp-uniform
    const int i0   = ih * IH;
    const int pix  = blockIdx.x * 128 + (tid & 127);
    const int grp  = pix >> 5;
    const int nb   = __ldg(nobj + b);
    int ni = nb - i0; ni = ni < 0 ? 0 : (ni > IH ? IH : ni);

    __shared__ ulonglong2 msh2[NI * 4];           // means, f32x2-packed
    __shared__ float smm[NI];
    __shared__ float red[8];
    __shared__ bool  sflag;

    for (int idx = tid; idx < NI * F; idx += 256)
        ((float*)msh2)[idx] = ((const float*)g_means)[b * NI * F + idx];
    if (tid < NI) smm[tid] = g_mm[b][tid];
    __syncthreads();

    float local = 0.f;
    if (ni > 0) {
        const float* ib = inp + (size_t)b * F * L + pix;
        unsigned long long p2[8];
#pragma unroll
        for (int j = 0; j < 8; j++) {
            float lo = ib[(size_t)(2 * j) * L];
            float hi = ib[(size_t)(2 * j + 1) * L];
            asm("mov.b64 %0,{%1,%2};" : "=l"(p2[j]) : "f"(lo), "f"(hi));
        }
        // pp = ||p||^2
        unsigned long long qa = 0ull, qb = 0ull;
#pragma unroll
        for (int q = 0; q < 4; q++) {
            asm("fma.rn.f32x2 %0,%1,%2,%3;" : "=l"(qa) : "l"(p2[2*q]),   "l"(p2[2*q]),   "l"(qa));
            asm("fma.rn.f32x2 %0,%1,%2,%3;" : "=l"(qb) : "l"(p2[2*q+1]), "l"(p2[2*q+1]), "l"(qb));
        }
        float plo, phi, plo2, phi2;
        asm("mov.b64 {%0,%1},%2;" : "=f"(plo),  "=f"(phi)  : "l"(qa));
        asm("mov.b64 {%0,%1},%2;" : "=f"(plo2), "=f"(phi2) : "l"(qb));
        const float pp = (plo + phi) + (plo2 + phi2);

        unsigned mw = (lane < IH) ? g_masks[b][grp][i0 + lane] : 0u;

#pragma unroll
        for (int j = 0; j < IH; j++) {
            if (j >= ni) break;
            unsigned mi = __shfl_sync(0xffffffffu, mw, j);
            if ((mi >> lane) & 1u) {
                unsigned long long da = 0ull, db = 0ull;
#pragma unroll
                for (int q = 0; q < 4; q++) {
                    ulonglong2 mv = msh2[(i0 + j) * 4 + q];
                    asm("fma.rn.f32x2 %0,%1,%2,%3;" : "=l"(da) : "l"(p2[2*q]),   "l"(mv.x), "l"(da));
                    asm("fma.rn.f32x2 %0,%1,%2,%3;" : "=l"(db) : "l"(p2[2*q+1]), "l"(mv.y), "l"(db));
                }
                float alo, ahi, blo, bhi;
                asm("mov.b64 {%0,%1},%2;" : "=f"(alo), "=f"(ahi) : "l"(da));
                asm("mov.b64 {%0,%1},%2;" : "=f"(blo), "=f"(bhi) : "l"(db));
                float dot = (alo + ahi) + (blo + bhi);
                float ss = fmaf(-2.f, dot, pp + smm[i0 + j]);
                if (ss > 0.25f) {                 // delta_v^2 (also filters fp-negatives)
                    float h = sqrtf(ss) - 0.5f;
                    local += h * h;
                }
            }
        }
    }

#pragma unroll
    for (int o = 16; o > 0; o >>= 1)
        local += __shfl_down_sync(0xffffffffu, local, o);
    if (lane == 0) red[warp] = local;
    __syncthreads();
    if (tid < 8) {
        float v = red[tid];
#pragma unroll
        for (int o = 4; o > 0; o >>= 1)
            v += __shfl_down_sync(0xffu, v, o);
        if (tid == 0) atomicAdd(&g_varnum[b], v);
    }

    // ---- last block: final scalar, then re-zero ----
    __threadfence();
    __syncthreads();
    if (tid == 0) sflag = (atomicAdd(&g_cnt2, 1u) == NBT - 1u);
    __syncthreads();
    if (!sflag) return;

    if (tid == 0) {
        float var_t = 0.f, dist_t = 0.f, reg_t = 0.f;
        for (int bb = 0; bb < BS; bb++) {
            var_t += g_varnum[bb] / g_varden[bb];
            float nf = (float)__ldg(nobj + bb);
            float denom = nf > 1.f ? nf * (nf - 1.f) : 1.f;
            dist_t += (nf > 1.f) ? g_hinge[bb] / denom : 0.f;
            reg_t += g_reg[bb] / nf;
        }
        out[0] = var_t / BS + dist_t / BS + 0.001f * (reg_t / BS);
    }
    __syncthreads();
    if (tid < BS) g_varnum[tid] = 0.f;
    if (tid == 0) g_cnt2 = 0u;
}

// ---------------- launch ----------------
extern "C" void kernel_launch(void* const* d_in, const int* in_sizes, int n_in,
                              void* d_out, int out_size) {
    const float* inp  = (const float*)d_in[0];   // (8,16,128,128) f32
    const int*   tgt  = (const int*)d_in[1];     // (8,24,128,128) i32
    const int*   nobj = (const int*)d_in[2];     // (8,1) i32
    (void)in_sizes; (void)n_in; (void)out_size;

    dim3 g(128, BS);                             // 1024 blocks each
    k_sums<<<g, 256>>>(inp, tgt, nobj);
    k_var<<<g, 256>>>(inp, nobj, (float*)d_out);
}